// round 1
// baseline (speedup 1.0000x reference)
#include <cuda_runtime.h>

#define NN 100000
#define EE 1600000
#define GG 1000
#define HH 64
#define BN_EPS 1e-5f

// ---------------- device scratch (no allocations allowed) ----------------
__device__ int   g_is64;
__device__ int   g_cnt[NN];
__device__ int   g_fill[NN];
__device__ int   g_rowptr[NN + 1];
__device__ int   g_col[EE];
__device__ float g_dinv[NN];
__device__ float g_bufA[NN * HH];
__device__ float g_bufB[NN * HH];
__device__ float g_hw[NN * HH];
__device__ int   g_bsum[128];
__device__ int   g_startg[GG + 1];
__device__ float g_pool[GG * 128];

// index loader handling int64-vs-int32 edge/batch buffers
__device__ __forceinline__ int ld_idx(const void* p, long i, int is64) {
    if (is64) return (int)((const long long*)p)[i];
    return ((const int*)p)[i];
}

// ---------------- dtype detection ----------------
__global__ void k_init() { g_is64 = 1; }

// If buffer is int64, every odd 32-bit word in the first E entries (src array)
// is the zero high-half. If int32, odd words are random node ids (nonzero w.h.p.).
__global__ void k_detect(const void* ei) {
    int e = blockIdx.x * blockDim.x + threadIdx.x;
    if (e >= EE) return;
    const int* w = (const int*)ei;
    if (w[2 * e + 1] != 0) g_is64 = 0;
}

// ---------------- CSR build ----------------
__global__ void k_zero() {
    int i = blockIdx.x * blockDim.x + threadIdx.x;
    if (i < NN) { g_cnt[i] = 0; g_fill[i] = 0; }
}

__global__ void k_count(const void* ei) {
    int e = blockIdx.x * blockDim.x + threadIdx.x;
    if (e >= EE) return;
    int is64 = g_is64;
    int d = ld_idx(ei, (long)EE + e, is64);
    atomicAdd(&g_cnt[d], 1);
}

__global__ void k_scan1() {
    __shared__ int sh[1024];
    int t = threadIdx.x;
    int i = blockIdx.x * 1024 + t;
    int v = (i < NN) ? g_cnt[i] : 0;
    sh[t] = v; __syncthreads();
#pragma unroll
    for (int off = 1; off < 1024; off <<= 1) {
        int x = 0; if (t >= off) x = sh[t - off];
        __syncthreads();
        sh[t] += x; __syncthreads();
    }
    if (i < NN) g_rowptr[i] = sh[t] - v;        // exclusive within block
    if (t == 1023) g_bsum[blockIdx.x] = sh[1023];
}

__global__ void k_scan2() {
    __shared__ int sh[128];
    int t = threadIdx.x;
    int nb = (NN + 1023) / 1024;
    int v = (t < nb) ? g_bsum[t] : 0;
    sh[t] = v; __syncthreads();
#pragma unroll
    for (int off = 1; off < 128; off <<= 1) {
        int x = 0; if (t >= off) x = sh[t - off];
        __syncthreads();
        sh[t] += x; __syncthreads();
    }
    if (t < nb) g_bsum[t] = sh[t] - v;          // exclusive block offsets
}

__global__ void k_scan3() {
    int i = blockIdx.x * blockDim.x + threadIdx.x;
    if (i < NN) g_rowptr[i] += g_bsum[i >> 10];
    if (i == 0) g_rowptr[NN] = EE;
}

__global__ void k_dinv() {
    int v = blockIdx.x * blockDim.x + threadIdx.x;
    if (v < NN) g_dinv[v] = rsqrtf((float)g_cnt[v] + 1.0f);
}

__global__ void k_fill(const void* ei) {
    int e = blockIdx.x * blockDim.x + threadIdx.x;
    if (e >= EE) return;
    int is64 = g_is64;
    int s = ld_idx(ei, e, is64);
    int d = ld_idx(ei, (long)EE + e, is64);
    int pos = g_rowptr[d] + atomicAdd(&g_fill[d], 1);
    g_col[pos] = s;
}

// ---------------- layer 0 matmul: hw = x(N,3) @ W0(3,64) ----------------
__global__ void k_mm_first(const float* __restrict__ x, const float* __restrict__ W0) {
    int tid = blockIdx.x * blockDim.x + threadIdx.x;
    if (tid >= NN * 32) return;
    int v = tid >> 5, j = tid & 31, c = 2 * j;
    float x0 = x[v * 3 + 0], x1 = x[v * 3 + 1], x2 = x[v * 3 + 2];
    float o0 = x0 * W0[c]     + x1 * W0[64 + c]     + x2 * W0[128 + c];
    float o1 = x0 * W0[c + 1] + x1 * W0[64 + c + 1] + x2 * W0[128 + c + 1];
    ((float2*)g_hw)[v * 32 + j] = make_float2(o0, o1);
}

// ---------------- 64x64 matmul: hw = h @ W ----------------
__global__ void k_mm64(int in_sel, const float* __restrict__ W) {
    __shared__ float2 sW[64 * 32];
    const float2* W2 = (const float2*)W;
    int tid = threadIdx.x;
    for (int i = tid; i < 64 * 32; i += 256) sW[i] = W2[i];
    __syncthreads();
    const float2* hin = (const float2*)(in_sel ? g_bufB : g_bufA);
    float2* hout = (float2*)g_hw;
    int warp = tid >> 5, lane = tid & 31;
    int base = blockIdx.x * 64;
    for (int n = warp; n < 64; n += 8) {
        int v = base + n;
        if (v >= NN) break;
        float2 hv = hin[v * 32 + lane];
        float2 acc = make_float2(0.f, 0.f);
#pragma unroll
        for (int k = 0; k < 32; ++k) {
            float a = __shfl_sync(0xffffffffu, hv.x, k);  // h[2k]
            float b = __shfl_sync(0xffffffffu, hv.y, k);  // h[2k+1]
            float2 w0 = sW[(2 * k) * 32 + lane];
            float2 w1 = sW[(2 * k + 1) * 32 + lane];
            acc.x = fmaf(a, w0.x, acc.x); acc.x = fmaf(b, w1.x, acc.x);
            acc.y = fmaf(a, w0.y, acc.y); acc.y = fmaf(b, w1.y, acc.y);
        }
        hout[v * 32 + lane] = acc;
    }
}

// ---------------- aggregation + self-loop + bias + BN + ReLU + residual ----------------
__global__ void k_agg(int prev_sel, int out_sel, int use_res,
                      const float* __restrict__ bias,
                      const float* __restrict__ gam, const float* __restrict__ bet,
                      const float* __restrict__ mea, const float* __restrict__ var) {
    int warp = threadIdx.x >> 5, lane = threadIdx.x & 31;
    int v = blockIdx.x * 8 + warp;
    if (v >= NN) return;
    const float2* hw2 = (const float2*)g_hw;
    int r0 = g_rowptr[v], r1 = g_rowptr[v + 1];
    float dv = g_dinv[v];
    float2 acc = make_float2(0.f, 0.f);
    for (int e = r0; e < r1; ++e) {
        int u = g_col[e];
        float w = dv * g_dinv[u];
        float2 m = hw2[u * 32 + lane];
        acc.x = fmaf(w, m.x, acc.x);
        acc.y = fmaf(w, m.y, acc.y);
    }
    float2 sl = hw2[v * 32 + lane];
    float sw = dv * dv;
    int c = 2 * lane;
    acc.x = fmaf(sw, sl.x, acc.x) + bias[c];
    acc.y = fmaf(sw, sl.y, acc.y) + bias[c + 1];
    float sc0 = gam[c] * rsqrtf(var[c] + BN_EPS);
    float sc1 = gam[c + 1] * rsqrtf(var[c + 1] + BN_EPS);
    float o0 = fmaxf((acc.x - mea[c]) * sc0 + bet[c], 0.f);
    float o1 = fmaxf((acc.y - mea[c + 1]) * sc1 + bet[c + 1], 0.f);
    if (use_res) {
        const float2* p2 = (const float2*)(prev_sel ? g_bufB : g_bufA);
        float2 pv = p2[v * 32 + lane];
        o0 += pv.x; o1 += pv.y;
    }
    float2* out2 = (float2*)(out_sel ? g_bufB : g_bufA);
    out2[v * 32 + lane] = make_float2(o0, o1);
}

// ---------------- segment boundaries (batch is sorted) ----------------
__global__ void k_bounds(const void* batch) {
    int v = blockIdx.x * blockDim.x + threadIdx.x;
    if (v >= NN) return;
    int is64 = g_is64;
    int b = ld_idx(batch, v, is64);
    if (v == 0) {
        for (int g = 0; g <= b; ++g) g_startg[g] = 0;
    } else {
        int pb = ld_idx(batch, v - 1, is64);
        for (int g = pb + 1; g <= b; ++g) g_startg[g] = v;
    }
    if (v == NN - 1) {
        for (int g = b + 1; g <= GG; ++g) g_startg[g] = NN;
    }
}

// ---------------- per-graph mean/max pooling (warp per graph) ----------------
__global__ void k_pool() {
    int warp = threadIdx.x >> 5, lane = threadIdx.x & 31;
    int g = blockIdx.x * 8 + warp;
    if (g >= GG) return;
    int s = g_startg[g], e = g_startg[g + 1];
    const float2* h2 = (const float2*)g_bufA;  // final layer output lives in bufA
    float2 sum = make_float2(0.f, 0.f);
    float2 mx = make_float2(-1e30f, -1e30f);
    for (int v = s; v < e; ++v) {
        float2 t = h2[v * 32 + lane];
        sum.x += t.x; sum.y += t.y;
        mx.x = fmaxf(mx.x, t.x); mx.y = fmaxf(mx.y, t.y);
    }
    float inv = (e > s) ? 1.0f / (float)(e - s) : 0.f;
    int c = 2 * lane;
    g_pool[g * 128 + c]        = sum.x * inv;
    g_pool[g * 128 + c + 1]    = sum.y * inv;
    g_pool[g * 128 + 64 + c]     = mx.x;
    g_pool[g * 128 + 64 + c + 1] = mx.y;
}

// ---------------- MLP head: [G,128] -> 128 -> 64 -> (gamma, beta) ----------------
__global__ void k_mlp(const float* __restrict__ fc1W, const float* __restrict__ fc1b,
                      const float* __restrict__ fc2W, const float* __restrict__ fc2b,
                      const float* __restrict__ fcgW, const float* __restrict__ fcgb,
                      const float* __restrict__ fcbW, const float* __restrict__ fcbb,
                      float* __restrict__ out) {
    __shared__ float srow[128];
    __shared__ float s1[128];
    __shared__ float s2[64];
    __shared__ float rg[64], rb[64];
    int g = blockIdx.x, t = threadIdx.x;
    srow[t] = g_pool[g * 128 + t];
    __syncthreads();
    float acc = fc1b[t];
#pragma unroll 8
    for (int k = 0; k < 128; ++k) acc = fmaf(srow[k], fc1W[k * 128 + t], acc);
    s1[t] = fmaxf(acc, 0.f);
    __syncthreads();
    if (t < 64) {
        float a = fc2b[t];
#pragma unroll 8
        for (int k = 0; k < 128; ++k) a = fmaf(s1[k], fc2W[k * 64 + t], a);
        float h2v = fmaxf(a, 0.f);
        s2[t] = h2v;
        rg[t] = h2v * fcgW[t];
        rb[t] = h2v * fcbW[t];
    }
    __syncthreads();
    if (t < 32) {
        float a = rg[t] + rg[t + 32];
        float b = rb[t] + rb[t + 32];
#pragma unroll
        for (int o = 16; o > 0; o >>= 1) {
            a += __shfl_down_sync(0xffffffffu, a, o);
            b += __shfl_down_sync(0xffffffffu, b, o);
        }
        if (t == 0) {
            out[g * 2 + 0] = a + fcgb[0];
            out[g * 2 + 1] = b + fcbb[0];
        }
    }
}

// ---------------- launch ----------------
extern "C" void kernel_launch(void* const* d_in, const int* in_sizes, int n_in,
                              void* d_out, int out_size) {
    const float* x    = (const float*)d_in[0];
    const void*  ei   = d_in[1];
    const void*  bat  = d_in[2];
    const float* W0   = (const float*)d_in[3];
    const float* b0   = (const float*)d_in[4];
    const float* Wh   = (const float*)d_in[5];
    const float* bh   = (const float*)d_in[6];
    const float* gam  = (const float*)d_in[7];
    const float* bet  = (const float*)d_in[8];
    const float* mea  = (const float*)d_in[9];
    const float* var  = (const float*)d_in[10];
    const float* fc1W = (const float*)d_in[11];
    const float* fc1b = (const float*)d_in[12];
    const float* fc2W = (const float*)d_in[13];
    const float* fc2b = (const float*)d_in[14];
    const float* fcgW = (const float*)d_in[15];
    const float* fcgb = (const float*)d_in[16];
    const float* fcbW = (const float*)d_in[17];
    const float* fcbb = (const float*)d_in[18];
    float* out = (float*)d_out;

    const int TB = 256;
    const int NB_N = (NN + TB - 1) / TB;
    const int NB_E = (EE + TB - 1) / TB;
    const int NB_SCAN = (NN + 1023) / 1024;

    k_init<<<1, 1>>>();
    k_detect<<<NB_E, TB>>>(ei);
    k_zero<<<NB_N, TB>>>();
    k_count<<<NB_E, TB>>>(ei);
    k_scan1<<<NB_SCAN, 1024>>>();
    k_scan2<<<1, 128>>>();
    k_scan3<<<NB_N, TB>>>();
    k_dinv<<<NB_N, TB>>>();
    k_fill<<<NB_E, TB>>>(ei);

    // layer 0: x -> hw -> agg -> bufA
    k_mm_first<<<(NN * 32 + TB - 1) / TB, TB>>>(x, W0);
    k_agg<<<(NN + 7) / 8, TB>>>(0, 0, 0, b0, gam, bet, mea, var);
    // layer 1: bufA -> hw -> agg(+bufA) -> bufB
    k_mm64<<<(NN + 63) / 64, TB>>>(0, Wh);
    k_agg<<<(NN + 7) / 8, TB>>>(0, 1, 1, bh, gam + 64, bet + 64, mea + 64, var + 64);
    // layer 2: bufB -> hw -> agg(+bufB) -> bufA
    k_mm64<<<(NN + 63) / 64, TB>>>(1, Wh + 64 * 64);
    k_agg<<<(NN + 7) / 8, TB>>>(1, 0, 1, bh + 64, gam + 128, bet + 128, mea + 128, var + 128);

    // pooling + head
    k_bounds<<<NB_N, TB>>>(bat);
    k_pool<<<(GG + 7) / 8, TB>>>();
    k_mlp<<<GG, 128>>>(fc1W, fc1b, fc2W, fc2b, fcgW, fcgb, fcbW, fcbb, out);
}

// round 2
// speedup vs baseline: 1.1441x; 1.1441x over previous
#include <cuda_runtime.h>
#include <cuda_fp16.h>

#define NN 100000
#define EE 1600000
#define GG 1000
#define BN_EPS 1e-5f

// ---------------- device scratch ----------------
__device__ int     g_is64;
__device__ int     g_cnt[NN];
__device__ int     g_fill[NN];
__device__ int     g_rowptr[NN + 1];
__device__ int2    g_cw[EE];          // (col, weight-bits) per edge, CSR order
__device__ float   g_dinv[NN];
__device__ float   g_bufA[NN * 64];
__device__ float   g_bufB[NN * 64];
__device__ __half2 g_h16A[NN * 32];
__device__ __half2 g_h16B[NN * 32];
__device__ int     g_bsum[128];
__device__ int     g_startg[GG + 1];
__device__ float   g_pool[GG * 128];

__device__ __forceinline__ int ld_idx(const void* p, long i, int is64) {
    if (is64) return (int)((const long long*)p)[i];
    return ((const int*)p)[i];
}

// ---------------- dtype detection (sampled, one block) ----------------
__global__ void k_detect(const void* ei) {
    __shared__ int sh_any;
    if (threadIdx.x == 0) sh_any = 0;
    __syncthreads();
    long stride = EE / 256;
    long e = (long)threadIdx.x * stride + 1;
    const int* w = (const int*)ei;
    if (w[2 * e + 1] != 0) sh_any = 1;   // benign race
    __syncthreads();
    if (threadIdx.x == 0) g_is64 = (sh_any == 0) ? 1 : 0;
}

// ---------------- CSR build ----------------
__global__ void k_zero() {
    int i = blockIdx.x * blockDim.x + threadIdx.x;
    if (i < NN) { g_cnt[i] = 0; g_fill[i] = 0; }
}

__global__ void k_count(const void* ei) {
    int e = blockIdx.x * blockDim.x + threadIdx.x;
    if (e >= EE) return;
    int d = ld_idx(ei, (long)EE + e, g_is64);
    atomicAdd(&g_cnt[d], 1);
}

__global__ void k_scan1() {
    __shared__ int sh[1024];
    int t = threadIdx.x;
    int i = blockIdx.x * 1024 + t;
    int v = (i < NN) ? g_cnt[i] : 0;
    sh[t] = v; __syncthreads();
#pragma unroll
    for (int off = 1; off < 1024; off <<= 1) {
        int x = 0; if (t >= off) x = sh[t - off];
        __syncthreads();
        sh[t] += x; __syncthreads();
    }
    if (i < NN) g_rowptr[i] = sh[t] - v;
    if (t == 1023) g_bsum[blockIdx.x] = sh[1023];
}

__global__ void k_scan2() {
    __shared__ int sh[128];
    int t = threadIdx.x;
    int nb = (NN + 1023) / 1024;
    int v = (t < nb) ? g_bsum[t] : 0;
    sh[t] = v; __syncthreads();
#pragma unroll
    for (int off = 1; off < 128; off <<= 1) {
        int x = 0; if (t >= off) x = sh[t - off];
        __syncthreads();
        sh[t] += x; __syncthreads();
    }
    if (t < nb) g_bsum[t] = sh[t] - v;
}

__global__ void k_scan3() {
    int i = blockIdx.x * blockDim.x + threadIdx.x;
    if (i < NN) {
        g_rowptr[i] += g_bsum[i >> 10];
        g_dinv[i] = rsqrtf((float)g_cnt[i] + 1.0f);
    }
    if (i == 0) g_rowptr[NN] = EE;
}

__global__ void k_fill(const void* ei) {
    int e = blockIdx.x * blockDim.x + threadIdx.x;
    if (e >= EE) return;
    int is64 = g_is64;
    int s = ld_idx(ei, e, is64);
    int d = ld_idx(ei, (long)EE + e, is64);
    int pos = g_rowptr[d] + atomicAdd(&g_fill[d], 1);
    float w = g_dinv[s] * g_dinv[d];
    g_cw[pos] = make_int2(s, __float_as_int(w));
}

// ---------------- layer 0: agg(x) -> @W0 -> BN -> ReLU -> bufA + h16A ----------------
__global__ void k_layer0(const float* __restrict__ x,
                         const float* __restrict__ W0, const float* __restrict__ b0,
                         const float* __restrict__ gam, const float* __restrict__ bet,
                         const float* __restrict__ mea, const float* __restrict__ var) {
    int warp = threadIdx.x >> 5, lane = threadIdx.x & 31;
    int v = blockIdx.x * 8 + warp;
    if (v >= NN) return;
    int r0 = g_rowptr[v], r1 = g_rowptr[v + 1];
    float a0 = 0.f, a1 = 0.f, a2 = 0.f;
    for (int e = r0 + lane; e < r1; e += 32) {
        int2 cw = g_cw[e];
        int u = cw.x; float w = __int_as_float(cw.y);
        a0 = fmaf(w, x[u * 3 + 0], a0);
        a1 = fmaf(w, x[u * 3 + 1], a1);
        a2 = fmaf(w, x[u * 3 + 2], a2);
    }
#pragma unroll
    for (int o = 16; o > 0; o >>= 1) {
        a0 += __shfl_xor_sync(0xffffffffu, a0, o);
        a1 += __shfl_xor_sync(0xffffffffu, a1, o);
        a2 += __shfl_xor_sync(0xffffffffu, a2, o);
    }
    float dv = g_dinv[v], sw = dv * dv;
    a0 = fmaf(sw, x[v * 3 + 0], a0);
    a1 = fmaf(sw, x[v * 3 + 1], a1);
    a2 = fmaf(sw, x[v * 3 + 2], a2);
    int c = 2 * lane;
    float o0 = a0 * W0[c]     + a1 * W0[64 + c]     + a2 * W0[128 + c]     + b0[c];
    float o1 = a0 * W0[c + 1] + a1 * W0[64 + c + 1] + a2 * W0[128 + c + 1] + b0[c + 1];
    o0 = fmaxf((o0 - mea[c])     * (gam[c]     * rsqrtf(var[c]     + BN_EPS)) + bet[c],     0.f);
    o1 = fmaxf((o1 - mea[c + 1]) * (gam[c + 1] * rsqrtf(var[c + 1] + BN_EPS)) + bet[c + 1], 0.f);
    ((float2*)g_bufA)[v * 32 + lane] = make_float2(o0, o1);
    g_h16A[v * 32 + lane] = __floats2half2_rn(o0, o1);
}

// ---------------- layers 1,2: fp16 gather + fused matmul + BN + ReLU + residual ----------------
__global__ void k_layer(int sel, int write16,
                        const float* __restrict__ W, const float* __restrict__ b,
                        const float* __restrict__ gam, const float* __restrict__ bet,
                        const float* __restrict__ mea, const float* __restrict__ var) {
    __shared__ float2 sW[64 * 32];
    const float2* W2 = (const float2*)W;
    for (int i = threadIdx.x; i < 2048; i += 256) sW[i] = W2[i];
    __syncthreads();
    int warp = threadIdx.x >> 5, lane = threadIdx.x & 31;
    int v = blockIdx.x * 8 + warp;
    if (v >= NN) return;
    const __half2* hin16 = sel ? g_h16B : g_h16A;
    const float2*  hin32 = (const float2*)(sel ? g_bufB : g_bufA);
    float2*        hout32 = (float2*)(sel ? g_bufA : g_bufB);
    __half2*       hout16 = sel ? g_h16A : g_h16B;

    int r0 = g_rowptr[v], r1 = g_rowptr[v + 1];
    float2 acc = make_float2(0.f, 0.f);
    for (int e = r0; e < r1; ++e) {
        int2 cw = g_cw[e];
        float w = __int_as_float(cw.y);
        float2 m = __half22float2(hin16[cw.x * 32 + lane]);
        acc.x = fmaf(w, m.x, acc.x);
        acc.y = fmaf(w, m.y, acc.y);
    }
    float dv = g_dinv[v], swt = dv * dv;
    float2 hv = hin32[v * 32 + lane];
    acc.x = fmaf(swt, hv.x, acc.x);
    acc.y = fmaf(swt, hv.y, acc.y);

    // out = acc @ W via warp shuffles
    float2 o = make_float2(0.f, 0.f);
#pragma unroll
    for (int k = 0; k < 32; ++k) {
        float a  = __shfl_sync(0xffffffffu, acc.x, k);   // feature 2k
        float bb = __shfl_sync(0xffffffffu, acc.y, k);   // feature 2k+1
        float2 w0 = sW[(2 * k) * 32 + lane];
        float2 w1 = sW[(2 * k + 1) * 32 + lane];
        o.x = fmaf(a, w0.x, o.x); o.x = fmaf(bb, w1.x, o.x);
        o.y = fmaf(a, w0.y, o.y); o.y = fmaf(bb, w1.y, o.y);
    }
    int c = 2 * lane;
    o.x += b[c]; o.y += b[c + 1];
    o.x = fmaxf((o.x - mea[c])     * (gam[c]     * rsqrtf(var[c]     + BN_EPS)) + bet[c],     0.f) + hv.x;
    o.y = fmaxf((o.y - mea[c + 1]) * (gam[c + 1] * rsqrtf(var[c + 1] + BN_EPS)) + bet[c + 1], 0.f) + hv.y;
    hout32[v * 32 + lane] = o;
    if (write16) hout16[v * 32 + lane] = __floats2half2_rn(o.x, o.y);
}

// ---------------- segment boundaries ----------------
__global__ void k_bounds(const void* batch) {
    int v = blockIdx.x * blockDim.x + threadIdx.x;
    if (v >= NN) return;
    int is64 = g_is64;
    int b = ld_idx(batch, v, is64);
    if (v == 0) {
        for (int g = 0; g <= b; ++g) g_startg[g] = 0;
    } else {
        int pb = ld_idx(batch, v - 1, is64);
        for (int g = pb + 1; g <= b; ++g) g_startg[g] = v;
    }
    if (v == NN - 1) {
        for (int g = b + 1; g <= GG; ++g) g_startg[g] = NN;
    }
}

// ---------------- pooling (final h lives in bufA) ----------------
__global__ void k_pool() {
    int warp = threadIdx.x >> 5, lane = threadIdx.x & 31;
    int g = blockIdx.x * 8 + warp;
    if (g >= GG) return;
    int s = g_startg[g], e = g_startg[g + 1];
    const float2* h2 = (const float2*)g_bufA;
    float2 sum = make_float2(0.f, 0.f);
    float2 mx = make_float2(-1e30f, -1e30f);
    for (int v = s; v < e; ++v) {
        float2 t = h2[v * 32 + lane];
        sum.x += t.x; sum.y += t.y;
        mx.x = fmaxf(mx.x, t.x); mx.y = fmaxf(mx.y, t.y);
    }
    float inv = (e > s) ? 1.0f / (float)(e - s) : 0.f;
    int c = 2 * lane;
    g_pool[g * 128 + c]          = sum.x * inv;
    g_pool[g * 128 + c + 1]      = sum.y * inv;
    g_pool[g * 128 + 64 + c]     = mx.x;
    g_pool[g * 128 + 64 + c + 1] = mx.y;
}

// ---------------- MLP head ----------------
__global__ void k_mlp(const float* __restrict__ fc1W, const float* __restrict__ fc1b,
                      const float* __restrict__ fc2W, const float* __restrict__ fc2b,
                      const float* __restrict__ fcgW, const float* __restrict__ fcgb,
                      const float* __restrict__ fcbW, const float* __restrict__ fcbb,
                      float* __restrict__ out) {
    __shared__ float srow[128];
    __shared__ float s1[128];
    __shared__ float rg[64], rb[64];
    int g = blockIdx.x, t = threadIdx.x;
    srow[t] = g_pool[g * 128 + t];
    __syncthreads();
    float acc = fc1b[t];
#pragma unroll 8
    for (int k = 0; k < 128; ++k) acc = fmaf(srow[k], fc1W[k * 128 + t], acc);
    s1[t] = fmaxf(acc, 0.f);
    __syncthreads();
    if (t < 64) {
        float a = fc2b[t];
#pragma unroll 8
        for (int k = 0; k < 128; ++k) a = fmaf(s1[k], fc2W[k * 64 + t], a);
        float h2v = fmaxf(a, 0.f);
        rg[t] = h2v * fcgW[t];
        rb[t] = h2v * fcbW[t];
    }
    __syncthreads();
    if (t < 32) {
        float a = rg[t] + rg[t + 32];
        float b = rb[t] + rb[t + 32];
#pragma unroll
        for (int o = 16; o > 0; o >>= 1) {
            a += __shfl_down_sync(0xffffffffu, a, o);
            b += __shfl_down_sync(0xffffffffu, b, o);
        }
        if (t == 0) {
            out[g * 2 + 0] = a + fcgb[0];
            out[g * 2 + 1] = b + fcbb[0];
        }
    }
}

// ---------------- launch ----------------
extern "C" void kernel_launch(void* const* d_in, const int* in_sizes, int n_in,
                              void* d_out, int out_size) {
    const float* x    = (const float*)d_in[0];
    const void*  ei   = d_in[1];
    const void*  bat  = d_in[2];
    const float* W0   = (const float*)d_in[3];
    const float* b0   = (const float*)d_in[4];
    const float* Wh   = (const float*)d_in[5];
    const float* bh   = (const float*)d_in[6];
    const float* gam  = (const float*)d_in[7];
    const float* bet  = (const float*)d_in[8];
    const float* mea  = (const float*)d_in[9];
    const float* var  = (const float*)d_in[10];
    const float* fc1W = (const float*)d_in[11];
    const float* fc1b = (const float*)d_in[12];
    const float* fc2W = (const float*)d_in[13];
    const float* fc2b = (const float*)d_in[14];
    const float* fcgW = (const float*)d_in[15];
    const float* fcgb = (const float*)d_in[16];
    const float* fcbW = (const float*)d_in[17];
    const float* fcbb = (const float*)d_in[18];
    float* out = (float*)d_out;

    const int TB = 256;
    const int NB_N = (NN + TB - 1) / TB;
    const int NB_E = (EE + TB - 1) / TB;
    const int NB_SCAN = (NN + 1023) / 1024;
    const int NB_NODE = (NN + 7) / 8;

    k_detect<<<1, 256>>>(ei);
    k_zero<<<NB_N, TB>>>();
    k_count<<<NB_E, TB>>>(ei);
    k_scan1<<<NB_SCAN, 1024>>>();
    k_scan2<<<1, 128>>>();
    k_scan3<<<NB_N, TB>>>();
    k_fill<<<NB_E, TB>>>(ei);

    // layer 0: gather x (3-wide) -> W0 -> BN/ReLU -> bufA + h16A
    k_layer0<<<NB_NODE, TB>>>(x, W0, b0, gam, bet, mea, var);
    // layer 1: A -> B (fp16 gather), residual
    k_layer<<<NB_NODE, TB>>>(0, 1, Wh,           bh,      gam + 64,  bet + 64,  mea + 64,  var + 64);
    // layer 2: B -> A (fp16 gather), residual, no half output needed
    k_layer<<<NB_NODE, TB>>>(1, 0, Wh + 64 * 64, bh + 64, gam + 128, bet + 128, mea + 128, var + 128);

    k_bounds<<<NB_N, TB>>>(bat);
    k_pool<<<(GG + 7) / 8, TB>>>();
    k_mlp<<<GG, 128>>>(fc1W, fc1b, fc2W, fc2b, fcgW, fcgb, fcbW, fcbb, out);
}

// round 3
// speedup vs baseline: 1.2071x; 1.0551x over previous
#include <cuda_runtime.h>
#include <cuda_fp16.h>

#define NN 100000
#define EE 1600000
#define GG 1000
#define BN_EPS 1e-5f

// ---------------- device scratch ----------------
__device__ int     g_is64;
__device__ int     g_cnt[NN];
__device__ int     g_fill[NN];
__device__ int     g_rowptr[NN + 1];
__device__ int2    g_cw[EE];
__device__ float   g_dinv[NN];
__device__ float   g_bufA[NN * 64];
__device__ float   g_bufB[NN * 64];
__device__ __half2 g_h16A[NN * 32];
__device__ __half2 g_h16B[NN * 32];
__device__ int     g_bsum[128];
__device__ int     g_startg[GG + 1];
__device__ float   g_pool[GG * 128];
// folded weights: W' = W * sc, b' = (b - mean)*sc + beta
__device__ float   g_W0f[3 * 64];
__device__ float   g_b0f[64];
__device__ float   g_Wf[2][64 * 64];
__device__ float   g_bf[2][64];

__device__ __forceinline__ int ld_idx(const void* p, long i, int is64) {
    if (is64) return (int)((const long long*)p)[i];
    return ((const int*)p)[i];
}

// ---------------- prep: detect dtype, zero counters, fold BN into weights ----------------
__global__ void k_prep(const void* ei,
                       const float* __restrict__ W0, const float* __restrict__ b0,
                       const float* __restrict__ Wh, const float* __restrict__ bh,
                       const float* __restrict__ gam, const float* __restrict__ bet,
                       const float* __restrict__ mea, const float* __restrict__ var) {
    int i = blockIdx.x * blockDim.x + threadIdx.x;
    if (i < NN) g_cnt[i] = 0;

    if (blockIdx.x == 0) {
        // detection: sample odd 32-bit words of src array; all-zero => int64
        __shared__ int sh_any;
        if (threadIdx.x == 0) sh_any = 0;
        __syncthreads();
        long stride = EE / 256;
        long e = (long)threadIdx.x * stride + 1;
        const int* w = (const int*)ei;
        if (w[2 * e + 1] != 0) sh_any = 1;
        __syncthreads();
        if (threadIdx.x == 0) g_is64 = (sh_any == 0) ? 1 : 0;
    } else if (blockIdx.x == 1) {
        // fold BN affine into weights/biases
        for (int t = threadIdx.x; t < 3 * 64; t += 256) {
            int c = t % 64;
            g_W0f[t] = W0[t] * (gam[c] * rsqrtf(var[c] + BN_EPS));
        }
        for (int t = threadIdx.x; t < 64; t += 256) {
            float sc = gam[t] * rsqrtf(var[t] + BN_EPS);
            g_b0f[t] = (b0[t] - mea[t]) * sc + bet[t];
        }
        for (int l = 0; l < 2; ++l) {
            const float* G = gam + 64 * (l + 1);
            const float* B = bet + 64 * (l + 1);
            const float* M = mea + 64 * (l + 1);
            const float* V = var + 64 * (l + 1);
            for (int t = threadIdx.x; t < 64 * 64; t += 256) {
                int c = t % 64;
                g_Wf[l][t] = Wh[l * 4096 + t] * (G[c] * rsqrtf(V[c] + BN_EPS));
            }
            for (int t = threadIdx.x; t < 64; t += 256) {
                float sc = G[t] * rsqrtf(V[t] + BN_EPS);
                g_bf[l][t] = (bh[l * 64 + t] - M[t]) * sc + B[t];
            }
        }
    }
}

// ---------------- count (2 edges/thread) + segment bounds, merged ----------------
#define NB_E2 ((EE + 511) / 512)
#define NB_N  ((NN + 255) / 256)

__global__ void k_count_bounds(const void* ei, const void* batch) {
    int is64 = g_is64;
    if (blockIdx.x < NB_E2) {
        int e = (blockIdx.x * 256 + threadIdx.x) * 2;
        if (e < EE) {
            int d0 = ld_idx(ei, (long)EE + e, is64);
            atomicAdd(&g_cnt[d0], 1);
            if (e + 1 < EE) {
                int d1 = ld_idx(ei, (long)EE + e + 1, is64);
                atomicAdd(&g_cnt[d1], 1);
            }
        }
    } else {
        int v = (blockIdx.x - NB_E2) * 256 + threadIdx.x;
        if (v >= NN) return;
        int b = ld_idx(batch, v, is64);
        if (v == 0) {
            for (int g = 0; g <= b; ++g) g_startg[g] = 0;
        } else {
            int pb = ld_idx(batch, v - 1, is64);
            for (int g = pb + 1; g <= b; ++g) g_startg[g] = v;
        }
        if (v == NN - 1) {
            for (int g = b + 1; g <= GG; ++g) g_startg[g] = NN;
        }
    }
}

// ---------------- scans ----------------
__global__ void k_scan1() {
    __shared__ int sh[1024];
    int t = threadIdx.x;
    int i = blockIdx.x * 1024 + t;
    int v = (i < NN) ? g_cnt[i] : 0;
    sh[t] = v; __syncthreads();
#pragma unroll
    for (int off = 1; off < 1024; off <<= 1) {
        int x = 0; if (t >= off) x = sh[t - off];
        __syncthreads();
        sh[t] += x; __syncthreads();
    }
    if (i < NN) g_rowptr[i] = sh[t] - v;
    if (t == 1023) g_bsum[blockIdx.x] = sh[1023];
}

__global__ void k_scan2() {
    __shared__ int sh[128];
    int t = threadIdx.x;
    int nb = (NN + 1023) / 1024;
    int v = (t < nb) ? g_bsum[t] : 0;
    sh[t] = v; __syncthreads();
#pragma unroll
    for (int off = 1; off < 128; off <<= 1) {
        int x = 0; if (t >= off) x = sh[t - off];
        __syncthreads();
        sh[t] += x; __syncthreads();
    }
    if (t < nb) g_bsum[t] = sh[t] - v;
}

__global__ void k_scan3() {
    int i = blockIdx.x * blockDim.x + threadIdx.x;
    if (i < NN) {
        int rp = g_rowptr[i] + g_bsum[i >> 10];
        g_rowptr[i] = rp;
        g_fill[i] = rp;                      // fill cursor starts at row base
        g_dinv[i] = rsqrtf((float)g_cnt[i] + 1.0f);
    }
    if (i == 0) g_rowptr[NN] = EE;
}

// ---------------- fill (2 edges/thread, atomic returns position) ----------------
__global__ void k_fill(const void* ei) {
    int is64 = g_is64;
    int e = (blockIdx.x * 256 + threadIdx.x) * 2;
    if (e >= EE) return;
#pragma unroll
    for (int q = 0; q < 2; ++q) {
        int ee = e + q;
        if (ee >= EE) break;
        int s = ld_idx(ei, ee, is64);
        int d = ld_idx(ei, (long)EE + ee, is64);
        int pos = atomicAdd(&g_fill[d], 1);
        float w = g_dinv[s] * g_dinv[d];
        g_cw[pos] = make_int2(s, __float_as_int(w));
    }
}

// ---------------- layer 0: agg(x) -> @W0f -> ReLU -> bufA + h16A ----------------
__global__ void k_layer0(const float* __restrict__ x) {
    int warp = threadIdx.x >> 5, lane = threadIdx.x & 31;
    int v = blockIdx.x * 8 + warp;
    if (v >= NN) return;
    int r0 = g_rowptr[v], r1 = g_rowptr[v + 1];
    float a0 = 0.f, a1 = 0.f, a2 = 0.f;
    for (int e = r0 + lane; e < r1; e += 32) {
        int2 cw = __ldg(&g_cw[e]);
        int u = cw.x; float w = __int_as_float(cw.y);
        a0 = fmaf(w, __ldg(&x[u * 3 + 0]), a0);
        a1 = fmaf(w, __ldg(&x[u * 3 + 1]), a1);
        a2 = fmaf(w, __ldg(&x[u * 3 + 2]), a2);
    }
#pragma unroll
    for (int o = 16; o > 0; o >>= 1) {
        a0 += __shfl_xor_sync(0xffffffffu, a0, o);
        a1 += __shfl_xor_sync(0xffffffffu, a1, o);
        a2 += __shfl_xor_sync(0xffffffffu, a2, o);
    }
    float dv = g_dinv[v], sw = dv * dv;
    a0 = fmaf(sw, x[v * 3 + 0], a0);
    a1 = fmaf(sw, x[v * 3 + 1], a1);
    a2 = fmaf(sw, x[v * 3 + 2], a2);
    int c = 2 * lane;
    float o0 = a0 * g_W0f[c]     + a1 * g_W0f[64 + c]     + a2 * g_W0f[128 + c]     + g_b0f[c];
    float o1 = a0 * g_W0f[c + 1] + a1 * g_W0f[64 + c + 1] + a2 * g_W0f[128 + c + 1] + g_b0f[c + 1];
    o0 = fmaxf(o0, 0.f);
    o1 = fmaxf(o1, 0.f);
    ((float2*)g_bufA)[v * 32 + lane] = make_float2(o0, o1);
    g_h16A[v * 32 + lane] = __floats2half2_rn(o0, o1);
}

// ---------------- layers 1,2: fp16 gather (x2 unrolled) + matmul + ReLU + residual ----------------
__global__ void k_layer(int sel, int write16, int lidx) {
    __shared__ float2 sW[64 * 32];
    const float2* W2 = (const float2*)g_Wf[lidx];
    for (int i = threadIdx.x; i < 2048; i += 256) sW[i] = W2[i];
    __syncthreads();
    int warp = threadIdx.x >> 5, lane = threadIdx.x & 31;
    int v = blockIdx.x * 8 + warp;
    if (v >= NN) return;
    const __half2* hin16 = sel ? g_h16B : g_h16A;
    const float2*  hin32 = (const float2*)(sel ? g_bufB : g_bufA);
    float2*        hout32 = (float2*)(sel ? g_bufA : g_bufB);
    __half2*       hout16 = sel ? g_h16A : g_h16B;
    const float*   b = g_bf[lidx];

    int r0 = g_rowptr[v], r1 = g_rowptr[v + 1];
    float2 acc = make_float2(0.f, 0.f);
    int e = r0;
    for (; e + 2 <= r1; e += 2) {
        int2 c0 = __ldg(&g_cw[e]);
        int2 c1 = __ldg(&g_cw[e + 1]);
        float2 m0 = __half22float2(__ldg(&hin16[c0.x * 32 + lane]));
        float2 m1 = __half22float2(__ldg(&hin16[c1.x * 32 + lane]));
        float w0 = __int_as_float(c0.y), w1 = __int_as_float(c1.y);
        acc.x = fmaf(w0, m0.x, acc.x); acc.y = fmaf(w0, m0.y, acc.y);
        acc.x = fmaf(w1, m1.x, acc.x); acc.y = fmaf(w1, m1.y, acc.y);
    }
    if (e < r1) {
        int2 c0 = __ldg(&g_cw[e]);
        float2 m0 = __half22float2(__ldg(&hin16[c0.x * 32 + lane]));
        float w0 = __int_as_float(c0.y);
        acc.x = fmaf(w0, m0.x, acc.x); acc.y = fmaf(w0, m0.y, acc.y);
    }
    float dv = g_dinv[v], swt = dv * dv;
    float2 hv = hin32[v * 32 + lane];
    acc.x = fmaf(swt, hv.x, acc.x);
    acc.y = fmaf(swt, hv.y, acc.y);

    float2 o = make_float2(0.f, 0.f);
#pragma unroll
    for (int k = 0; k < 32; ++k) {
        float a  = __shfl_sync(0xffffffffu, acc.x, k);
        float bb = __shfl_sync(0xffffffffu, acc.y, k);
        float2 w0 = sW[(2 * k) * 32 + lane];
        float2 w1 = sW[(2 * k + 1) * 32 + lane];
        o.x = fmaf(a, w0.x, o.x); o.x = fmaf(bb, w1.x, o.x);
        o.y = fmaf(a, w0.y, o.y); o.y = fmaf(bb, w1.y, o.y);
    }
    int c = 2 * lane;
    o.x = fmaxf(o.x + b[c],     0.f) + hv.x;
    o.y = fmaxf(o.y + b[c + 1], 0.f) + hv.y;
    hout32[v * 32 + lane] = o;
    if (write16) hout16[v * 32 + lane] = __floats2half2_rn(o.x, o.y);
}

// ---------------- pooling (final h lives in bufA) ----------------
__global__ void k_pool() {
    int warp = threadIdx.x >> 5, lane = threadIdx.x & 31;
    int g = blockIdx.x * 8 + warp;
    if (g >= GG) return;
    int s = g_startg[g], e = g_startg[g + 1];
    const float2* h2 = (const float2*)g_bufA;
    float2 sum = make_float2(0.f, 0.f);
    float2 mx = make_float2(-1e30f, -1e30f);
    for (int v = s; v < e; ++v) {
        float2 t = __ldg(&h2[v * 32 + lane]);
        sum.x += t.x; sum.y += t.y;
        mx.x = fmaxf(mx.x, t.x); mx.y = fmaxf(mx.y, t.y);
    }
    float inv = (e > s) ? 1.0f / (float)(e - s) : 0.f;
    int c = 2 * lane;
    g_pool[g * 128 + c]          = sum.x * inv;
    g_pool[g * 128 + c + 1]      = sum.y * inv;
    g_pool[g * 128 + 64 + c]     = mx.x;
    g_pool[g * 128 + 64 + c + 1] = mx.y;
}

// ---------------- MLP head ----------------
__global__ void k_mlp(const float* __restrict__ fc1W, const float* __restrict__ fc1b,
                      const float* __restrict__ fc2W, const float* __restrict__ fc2b,
                      const float* __restrict__ fcgW, const float* __restrict__ fcgb,
                      const float* __restrict__ fcbW, const float* __restrict__ fcbb,
                      float* __restrict__ out) {
    __shared__ float srow[128];
    __shared__ float s1[128];
    __shared__ float rg[64], rb[64];
    int g = blockIdx.x, t = threadIdx.x;
    srow[t] = g_pool[g * 128 + t];
    __syncthreads();
    float acc = fc1b[t];
#pragma unroll 8
    for (int k = 0; k < 128; ++k) acc = fmaf(srow[k], fc1W[k * 128 + t], acc);
    s1[t] = fmaxf(acc, 0.f);
    __syncthreads();
    if (t < 64) {
        float a = fc2b[t];
#pragma unroll 8
        for (int k = 0; k < 128; ++k) a = fmaf(s1[k], fc2W[k * 64 + t], a);
        float h2v = fmaxf(a, 0.f);
        rg[t] = h2v * fcgW[t];
        rb[t] = h2v * fcbW[t];
    }
    __syncthreads();
    if (t < 32) {
        float a = rg[t] + rg[t + 32];
        float b = rb[t] + rb[t + 32];
#pragma unroll
        for (int o = 16; o > 0; o >>= 1) {
            a += __shfl_down_sync(0xffffffffu, a, o);
            b += __shfl_down_sync(0xffffffffu, b, o);
        }
        if (t == 0) {
            out[g * 2 + 0] = a + fcgb[0];
            out[g * 2 + 1] = b + fcbb[0];
        }
    }
}

// ---------------- launch ----------------
extern "C" void kernel_launch(void* const* d_in, const int* in_sizes, int n_in,
                              void* d_out, int out_size) {
    const float* x    = (const float*)d_in[0];
    const void*  ei   = d_in[1];
    const void*  bat  = d_in[2];
    const float* W0   = (const float*)d_in[3];
    const float* b0   = (const float*)d_in[4];
    const float* Wh   = (const float*)d_in[5];
    const float* bh   = (const float*)d_in[6];
    const float* gam  = (const float*)d_in[7];
    const float* bet  = (const float*)d_in[8];
    const float* mea  = (const float*)d_in[9];
    const float* var  = (const float*)d_in[10];
    const float* fc1W = (const float*)d_in[11];
    const float* fc1b = (const float*)d_in[12];
    const float* fc2W = (const float*)d_in[13];
    const float* fc2b = (const float*)d_in[14];
    const float* fcgW = (const float*)d_in[15];
    const float* fcgb = (const float*)d_in[16];
    const float* fcbW = (const float*)d_in[17];
    const float* fcbb = (const float*)d_in[18];
    float* out = (float*)d_out;

    const int TB = 256;
    const int NB_SCAN = (NN + 1023) / 1024;
    const int NB_NODE = (NN + 7) / 8;

    k_prep<<<NB_N, TB>>>(ei, W0, b0, Wh, bh, gam, bet, mea, var);
    k_count_bounds<<<NB_E2 + NB_N, TB>>>(ei, bat);
    k_scan1<<<NB_SCAN, 1024>>>();
    k_scan2<<<1, 128>>>();
    k_scan3<<<NB_N, TB>>>();
    k_fill<<<NB_E2, TB>>>(ei);

    k_layer0<<<NB_NODE, TB>>>(x);
    k_layer<<<NB_NODE, TB>>>(0, 1, 0);   // A -> B
    k_layer<<<NB_NODE, TB>>>(1, 0, 1);   // B -> A

    k_pool<<<(GG + 7) / 8, TB>>>();
    k_mlp<<<GG, 128>>>(fc1W, fc1b, fc2W, fc2b, fcgW, fcgb, fcbW, fcbb, out);
}